// round 10
// baseline (speedup 1.0000x reference)
#include <cuda_runtime.h>

#define BB 256
#define SS 512
#define TT 128
#define C0 5.5f   // warmup anchor slope guess (self-corrected after 8 steps)

// Scratch (no allocations allowed in kernel_launch)
__device__ __align__(16) float g_ET[TT * TT];  // g_ET[t*TT+i] = exp(trans[i][t])
__device__ float g_gold[BB];
__device__ float g_logZ[BB];
__device__ int   g_tagStride;      // 1 = int32 tags, 2 = int64 tags

// ---------------------------------------------------------------------------
// Kernel 0: detect tag dtype (odd 32-bit words all zero => int64 buffer)
// ---------------------------------------------------------------------------
__global__ void detect_tags_kernel(const unsigned int* __restrict__ tags32) {
    unsigned int acc = 0;
    for (int i = threadIdx.x; i < 256; i += 32)
        acc |= tags32[2 * i + 1];
    #pragma unroll
    for (int o = 16; o > 0; o >>= 1)
        acc |= __shfl_xor_sync(0xffffffffu, acc, o);
    if (threadIdx.x == 0) g_tagStride = (acc == 0u) ? 2 : 1;
}

// ---------------------------------------------------------------------------
// Kernel 1: g_ET[t][i] = exp(trans[i][t])   (transposed: column t contiguous)
// ---------------------------------------------------------------------------
__global__ void expT_kernel(const float* __restrict__ trans) {
    int i = blockIdx.x * blockDim.x + threadIdx.x;
    if (i < TT * TT) {
        int r = i >> 7;
        int c = i & (TT - 1);
        g_ET[c * TT + r] = __expf(trans[i]);
    }
}

// ---------------------------------------------------------------------------
// Kernel 2: gold score per batch
// ---------------------------------------------------------------------------
__global__ void gold_kernel(const float* __restrict__ emis,
                            const int* __restrict__ tags,
                            const float* __restrict__ trans) {
    int b = blockIdx.x;
    int tid = threadIdx.x;
    int lane = tid & 31;
    int wid = tid >> 5;

    const int stride = g_tagStride;
    const int* tg = tags + b * SS * stride;
    const float* eb = emis + (size_t)b * SS * TT;

    float sum = 0.f;
    for (int s = tid; s < SS; s += blockDim.x) {
        int cur = tg[s * stride];
        sum += eb[s * TT + cur];
        if (s < SS - 1) {
            int nxt = tg[(s + 1) * stride];
            sum += trans[cur * TT + nxt];
        }
    }
    #pragma unroll
    for (int o = 16; o > 0; o >>= 1)
        sum += __shfl_xor_sync(0xffffffffu, sum, o);
    __shared__ float red[4];
    if (lane == 0) red[wid] = sum;
    __syncthreads();
    if (tid == 0) g_gold[b] = red[0] + red[1] + red[2] + red[3];
}

// ---------------------------------------------------------------------------
// Kernel 3: forward algorithm, TWO batches per CTA, interleaved per thread.
// Grid = 128 CTAs x 256 threads. Thread k: state t = k>>1, half h = k&1,
// owns E[64h..64h+64) of column t (32 packed f32x2 regs), and carries the
// recursion for BOTH batches 2*cb and 2*cb+1 -> two independent dependency
// chains per thread fill every latency bubble (LDS return, FFMA chain, STS).
//
// Scaled state per batch: P_s[t] = exp(alpha_s[t] - M_s).
//   acc_s[t]   = sum_i P_{s-1}[i] * E[i][t]      (half-dot + shfl_xor(1))
//   alpha_s[t] = log(acc_s[t]) + M_{s-1} + e_s[t]
//   P_s[t]     = acc_s[t] * exp(e_s[t] + M_{s-1} - M_s)
// Anchors M_s published 8 steps ahead by thread 0 (lag-8 slope prediction;
// algebra exact for any block-consistent anchors; only keeps exp in range).
// One __syncthreads per step covers both batches.
// ---------------------------------------------------------------------------
__global__ void __launch_bounds__(256, 1) forward_kernel(const float* __restrict__ emis) {
    int cb = blockIdx.x;          // batch pair: batches 2cb, 2cb+1
    int k = threadIdx.x;
    int t = k >> 1;
    int h = k & 1;
    int lane = k & 31;
    int wid = k >> 5;

    __shared__ __align__(16) float sp[2][2][136];  // [batch][parity][padded 128]
    __shared__ float moff[2][16];
    __shared__ float ahist[2][8];
    __shared__ float smax[8];
    __shared__ float ssum[8];

    // E half-column: 64 floats = 32 packed f32x2
    unsigned long long Ep[32];
    {
        const ulonglong2* ec = (const ulonglong2*)(g_ET + t * TT + 64 * h);
        #pragma unroll
        for (int j = 0; j < 16; j++) {
            ulonglong2 v = ec[j];
            Ep[2 * j]     = v.x;
            Ep[2 * j + 1] = v.y;
        }
    }

    const float* eb0 = emis + (size_t)(2 * cb) * SS * TT;
    const float* eb1 = eb0 + (size_t)SS * TT;
    const int pos = (t < 64) ? t : t + 4;          // padded position

    // --- init both batches
    float e0A = eb0[t];
    float e0B = eb1[t];
    if (k == 0) {
        ahist[0][0] = e0A;  ahist[1][0] = e0B;
        #pragma unroll
        for (int s = 0; s <= 8; s++) {
            moff[0][s] = e0A + (float)s * C0;
            moff[1][s] = e0B + (float)s * C0;
        }
    }
    __syncthreads();
    float mpA = moff[0][0], mpB = moff[1][0];      // M_0 per batch
    if (h == 0) {
        sp[0][1][pos] = __expf(e0A - mpA);         // P_0, read at s=1
        sp[1][1][pos] = __expf(e0B - mpB);
    }
    float abaseA = e0A, abaseB = e0B;              // used only by k==0

    // emission pipeline, 2 deep, per batch
    float ecA = eb0[TT + t],     ecB = eb1[TT + t];
    float n1A = eb0[2 * TT + t], n1B = eb1[2 * TT + t];

    float zA = 0.f, zB = 0.f;

    for (int s = 1; s < SS; s++) {
        float n2A = 0.f, n2B = 0.f;
        if (s + 2 < SS) {
            n2A = eb0[(s + 2) * TT + t];
            n2B = eb1[(s + 2) * TT + t];
        }

        __syncthreads();                    // the ONLY barrier per step
        float mcA = moff[0][s & 15];
        float mcB = moff[1][s & 15];
        float wA = __expf(ecA + (mpA - mcA));
        float wB = __expf(ecB + (mpB - mcB));

        // interleaved half-dots for both batches: 32 LDS.128, 64 FFMA2
        const ulonglong2* pbA = (const ulonglong2*)(sp[0][s & 1] + 68 * h);
        const ulonglong2* pbB = (const ulonglong2*)(sp[1][s & 1] + 68 * h);
        unsigned long long a0 = 0ull, a1 = 0ull, a2 = 0ull, a3 = 0ull;
        unsigned long long b0 = 0ull, b1 = 0ull, b2 = 0ull, b3 = 0ull;
        #pragma unroll
        for (int j = 0; j < 16; j += 2) {
            ulonglong2 pvA = pbA[j];
            ulonglong2 pwA = pbA[j + 1];
            ulonglong2 pvB = pbB[j];
            ulonglong2 pwB = pbB[j + 1];
            asm("fma.rn.f32x2 %0, %1, %2, %0;" : "+l"(a0) : "l"(pvA.x), "l"(Ep[2 * j]));
            asm("fma.rn.f32x2 %0, %1, %2, %0;" : "+l"(b0) : "l"(pvB.x), "l"(Ep[2 * j]));
            asm("fma.rn.f32x2 %0, %1, %2, %0;" : "+l"(a1) : "l"(pvA.y), "l"(Ep[2 * j + 1]));
            asm("fma.rn.f32x2 %0, %1, %2, %0;" : "+l"(b1) : "l"(pvB.y), "l"(Ep[2 * j + 1]));
            asm("fma.rn.f32x2 %0, %1, %2, %0;" : "+l"(a2) : "l"(pwA.x), "l"(Ep[2 * j + 2]));
            asm("fma.rn.f32x2 %0, %1, %2, %0;" : "+l"(b2) : "l"(pwB.x), "l"(Ep[2 * j + 2]));
            asm("fma.rn.f32x2 %0, %1, %2, %0;" : "+l"(a3) : "l"(pwA.y), "l"(Ep[2 * j + 3]));
            asm("fma.rn.f32x2 %0, %1, %2, %0;" : "+l"(b3) : "l"(pwB.y), "l"(Ep[2 * j + 3]));
        }
        float xl, xh, yl, yh, ul, uh, vl, vh;
        asm("mov.b64 {%0,%1}, %2;" : "=f"(xl), "=f"(xh) : "l"(a0));
        asm("mov.b64 {%0,%1}, %2;" : "=f"(yl), "=f"(yh) : "l"(a1));
        asm("mov.b64 {%0,%1}, %2;" : "=f"(ul), "=f"(uh) : "l"(a2));
        asm("mov.b64 {%0,%1}, %2;" : "=f"(vl), "=f"(vh) : "l"(a3));
        float accA = ((xl + xh) + (yl + yh)) + ((ul + uh) + (vl + vh));
        asm("mov.b64 {%0,%1}, %2;" : "=f"(xl), "=f"(xh) : "l"(b0));
        asm("mov.b64 {%0,%1}, %2;" : "=f"(yl), "=f"(yh) : "l"(b1));
        asm("mov.b64 {%0,%1}, %2;" : "=f"(ul), "=f"(uh) : "l"(b2));
        asm("mov.b64 {%0,%1}, %2;" : "=f"(vl), "=f"(vh) : "l"(b3));
        float accB = ((xl + xh) + (yl + yh)) + ((ul + uh) + (vl + vh));

        accA += __shfl_xor_sync(0xffffffffu, accA, 1);
        accB += __shfl_xor_sync(0xffffffffu, accB, 1);

        if (s == SS - 1) {   // mpA/mpB still the shift of the consumed buffer
            zA = __logf(accA) + mpA + ecA;
            zB = __logf(accB) + mpB + ecB;
            break;
        }

        if (h == 0) {
            sp[0][(s + 1) & 1][pos] = accA * wA;
            sp[1][(s + 1) & 1][pos] = accB * wB;
        }

        if (k == 0) {   // publish M_{s+8} for both batches (off the path)
            float al0 = __logf(accA) + mpA + ecA;
            float bl0 = __logf(accB) + mpB + ecB;
            float dA = (s >= 8) ? (al0 - ahist[0][s & 7]) * 0.125f
                                : __fdividef(al0 - abaseA, (float)s);
            float dB = (s >= 8) ? (bl0 - ahist[1][s & 7]) * 0.125f
                                : __fdividef(bl0 - abaseB, (float)s);
            moff[0][(s + 8) & 15] = al0 + 7.f * dA;
            moff[1][(s + 8) & 15] = bl0 + 7.f * dB;
            ahist[0][s & 7] = al0;
            ahist[1][s & 7] = bl0;
        }

        mpA = mcA; mpB = mcB;
        ecA = n1A; n1A = n2A;
        ecB = n1B; n1B = n2B;
    }

    // ---- two logsumexps (h==0 threads hold valid z) ----
    #pragma unroll
    for (int bi = 0; bi < 2; bi++) {
        float z = (h == 0) ? (bi == 0 ? zA : zB) : -1e30f;
        float mx = z;
        #pragma unroll
        for (int o = 16; o > 0; o >>= 1)
            mx = fmaxf(mx, __shfl_xor_sync(0xffffffffu, mx, o));
        if (lane == 0) smax[wid] = mx;
        __syncthreads();
        mx = smax[0];
        #pragma unroll
        for (int wv = 1; wv < 8; wv++) mx = fmaxf(mx, smax[wv]);

        float v = (h == 0) ? __expf(z - mx) : 0.f;
        #pragma unroll
        for (int o = 16; o > 0; o >>= 1)
            v += __shfl_xor_sync(0xffffffffu, v, o);
        if (lane == 0) ssum[wid] = v;
        __syncthreads();
        if (k == 0) {
            float total = 0.f;
            #pragma unroll
            for (int wv = 0; wv < 8; wv++) total += ssum[wv];
            g_logZ[2 * cb + bi] = __logf(total) + mx;
        }
        __syncthreads();   // smax/ssum reuse
    }
}

// ---------------------------------------------------------------------------
// Kernel 4: final scalar: mean_b(-gold[b] + logZ[b])
// ---------------------------------------------------------------------------
__global__ void finalize_kernel(float* __restrict__ out) {
    int t = threadIdx.x;   // 256 threads
    int lane = t & 31;
    int wid = t >> 5;

    float v = -g_gold[t] + g_logZ[t];
    #pragma unroll
    for (int o = 16; o > 0; o >>= 1)
        v += __shfl_xor_sync(0xffffffffu, v, o);
    __shared__ float red[8];
    if (lane == 0) red[wid] = v;
    __syncthreads();
    if (t == 0) {
        float total = 0.f;
        #pragma unroll
        for (int w = 0; w < 8; w++) total += red[w];
        out[0] = total / (float)BB;
    }
}

// ---------------------------------------------------------------------------
extern "C" void kernel_launch(void* const* d_in, const int* in_sizes, int n_in,
                              void* d_out, int out_size) {
    const float* emis  = (const float*)d_in[0];   // (256, 512, 128) f32
    const int*   tags  = (const int*)d_in[1];     // (256, 512) i32/i64 (detected)
    const float* trans = (const float*)d_in[2];   // (128, 128) f32
    float* out = (float*)d_out;

    detect_tags_kernel<<<1, 32>>>((const unsigned int*)tags);
    expT_kernel<<<(TT * TT + 127) / 128, 128>>>(trans);
    gold_kernel<<<BB, 128>>>(emis, tags, trans);
    forward_kernel<<<BB / 2, 256>>>(emis);
    finalize_kernel<<<1, BB>>>(out);
}